// round 9
// baseline (speedup 1.0000x reference)
#include <cuda_runtime.h>
#include <stdint.h>

// Problem constants (fixed by the dataset).
#define Nn 20000
#define Ee 5000
#define Ff 128
#define NODE_CAP 256   // max edges per node (Binom(5000,.01): mean 50, max ~81)
#define EDGE_CAP 512   // max nodes per edge (Binom(20000,.01): mean 200, max ~260)
#define ROW_BYTES (Ee * 4)   // 20000 B, 16B-aligned stride

// ---------------- device scratch (no allocations allowed) ----------------
__device__ float g_Xw[Nn * Ff];                        // 10.24 MB
__device__ float g_M[Ee * Ff];                         //  2.56 MB
__device__ int   g_node_cnt[Nn];
__device__ int   g_edge_cnt[Ee];    // zero at start of every run (see k_node_gather)
__device__ unsigned short g_node_edges[Nn * NODE_CAP];
__device__ unsigned short g_edge_nodes[Ee * EDGE_CAP];

__device__ __forceinline__ float4 f4add(float4 a, float4 b) {
    a.x += b.x; a.y += b.y; a.z += b.z; a.w += b.w; return a;
}

__device__ __forceinline__ uint32_t smem_u32(const void* p) {
    uint32_t a;
    asm("{ .reg .u64 t; cvta.to.shared.u64 t, %1; cvt.u32.u64 %0, t; }"
        : "=r"(a) : "l"(p));
    return a;
}

__device__ __forceinline__ void mbar_wait0(uint32_t mbar) {
    asm volatile(
        "{\n\t"
        ".reg .pred P;\n\t"
        "W%=:\n\t"
        "mbarrier.try_wait.parity.acquire.cta.shared::cta.b64 P, [%0], 0;\n\t"
        "@P bra D%=;\n\t"
        "bra W%=;\n\t"
        "D%=:\n\t"
        "}" :: "r"(mbar) : "memory");
}

// ---------------- nop probe (keeps the scan in the profiled slot) --------
__global__ void k_nop() {}

// ---------------- K1: Xw = X @ W, 4x4 register micro-tile ----------------
__global__ __launch_bounds__(256) void k_xw(const float* __restrict__ X,
                                            const float* __restrict__ W) {
    __shared__ float xs[32][Ff];   // 16 KB X tile
    int tx = threadIdx.x;          // 0..31 (col group)
    int ty = threadIdx.y;          // 0..7  (row group)
    int tid = ty * 32 + tx;
    int row0 = blockIdx.x * 32;

    const float4* X4 = (const float4*)(X + (size_t)row0 * Ff);
#pragma unroll
    for (int k = 0; k < 4; k++) {
        int v = tid + k * 256;
        int r = v >> 5, c4 = v & 31;
        ((float4*)&xs[r][0])[c4] = X4[r * 32 + c4];
    }
    __syncthreads();

    const float4* W4 = (const float4*)W;
    float4 acc0 = {0,0,0,0}, acc1 = {0,0,0,0}, acc2 = {0,0,0,0}, acc3 = {0,0,0,0};
    int r0 = 4 * ty;

#pragma unroll 4
    for (int k = 0; k < Ff; k++) {
        float4 w = W4[k * 32 + tx];
        float x0 = xs[r0 + 0][k];
        float x1 = xs[r0 + 1][k];
        float x2 = xs[r0 + 2][k];
        float x3 = xs[r0 + 3][k];
        acc0.x += x0 * w.x; acc0.y += x0 * w.y; acc0.z += x0 * w.z; acc0.w += x0 * w.w;
        acc1.x += x1 * w.x; acc1.y += x1 * w.y; acc1.z += x1 * w.z; acc1.w += x1 * w.w;
        acc2.x += x2 * w.x; acc2.y += x2 * w.y; acc2.z += x2 * w.z; acc2.w += x2 * w.w;
        acc3.x += x3 * w.x; acc3.y += x3 * w.y; acc3.z += x3 * w.z; acc3.w += x3 * w.w;
    }

    float4* O4 = (float4*)g_Xw;
    int orow = row0 + r0;
    O4[(orow + 0) * 32 + tx] = acc0;
    O4[(orow + 1) * 32 + tx] = acc1;
    O4[(orow + 2) * 32 + tx] = acc2;
    O4[(orow + 3) * 32 + tx] = acc3;
}

// ---------------- K2: 2-row pipelined TMA scan of H ----------------------
// Each block handles rows 2b and 2b+1. Both TMA bulk loads are issued at
// block start; processing of row 0 overlaps row 1's in-flight load, keeping
// DRAM busy through the processing phases. OR-test skips all-zero 16B chunks
// (~96% of them). H entries are exactly 0.0f or 1.0f -> integer compare exact.
__global__ __launch_bounds__(256) void k_scan_h(const float* __restrict__ H) {
    __shared__ alignas(16) uint4 buf[2][Ee / 4];   // 2 x 20000 B
    __shared__ uint64_t mbar_store[2];
    __shared__ int s_cnt[2];
    int tid = threadIdx.x;
    int n0 = blockIdx.x * 2;

    uint32_t mb0 = smem_u32(&mbar_store[0]);
    uint32_t mb1 = smem_u32(&mbar_store[1]);

    if (tid == 0) {
        s_cnt[0] = 0; s_cnt[1] = 0;
        asm volatile("mbarrier.init.shared.b64 [%0], 1;" :: "r"(mb0) : "memory");
        asm volatile("mbarrier.init.shared.b64 [%0], 1;" :: "r"(mb1) : "memory");
    }
    __syncthreads();

    if (tid == 0) {
        asm volatile("mbarrier.arrive.expect_tx.shared.b64 _, [%0], %1;"
                     :: "r"(mb0), "r"((uint32_t)ROW_BYTES) : "memory");
        asm volatile(
            "cp.async.bulk.shared::cta.global.mbarrier::complete_tx::bytes "
            "[%0], [%1], %2, [%3];"
            :: "r"(smem_u32(buf[0])), "l"(H + (size_t)n0 * Ee),
               "r"((uint32_t)ROW_BYTES), "r"(mb0) : "memory");
        asm volatile("mbarrier.arrive.expect_tx.shared.b64 _, [%0], %1;"
                     :: "r"(mb1), "r"((uint32_t)ROW_BYTES) : "memory");
        asm volatile(
            "cp.async.bulk.shared::cta.global.mbarrier::complete_tx::bytes "
            "[%0], [%1], %2, [%3];"
            :: "r"(smem_u32(buf[1])), "l"(H + (size_t)(n0 + 1) * Ee),
               "r"((uint32_t)ROW_BYTES), "r"(mb1) : "memory");
    }

    const int nvec = Ee / 4;  // 1250
#pragma unroll
    for (int s = 0; s < 2; s++) {
        int n = n0 + s;
        mbar_wait0(s == 0 ? mb0 : mb1);
#pragma unroll
        for (int k = 0; k < 5; k++) {
            int i4 = tid + k * 256;
            if (i4 < nvec) {
                uint4 v = buf[s][i4];
                if ((v.x | v.y | v.z | v.w) != 0u) {
                    unsigned vals[4] = {v.x, v.y, v.z, v.w};
#pragma unroll
                    for (int c = 0; c < 4; c++) {
                        if (vals[c] != 0u) {
                            int e = i4 * 4 + c;
                            int j = atomicAdd(&s_cnt[s], 1);
                            if (j < NODE_CAP)
                                g_node_edges[n * NODE_CAP + j] = (unsigned short)e;
                            int kk = atomicAdd(&g_edge_cnt[e], 1);
                            if (kk < EDGE_CAP)
                                g_edge_nodes[e * EDGE_CAP + kk] = (unsigned short)n;
                        }
                    }
                }
            }
        }
    }
    __syncthreads();
    if (tid == 0) {
        g_node_cnt[n0]     = s_cnt[0];
        g_node_cnt[n0 + 1] = s_cnt[1];
    }
}

// ---------------- K3: block-per-edge, 4 warps (proven shape) -------------
__global__ __launch_bounds__(128) void k_edge_gather() {
    __shared__ unsigned short s_list[EDGE_CAP];
    __shared__ float4 s_red[4][32];
    int e = blockIdx.x;
    int tid = threadIdx.x;
    int w = tid >> 5, l = tid & 31;
    int cnt = g_edge_cnt[e];
    int L = cnt < EDGE_CAP ? cnt : EDGE_CAP;
    for (int i = tid; i < L; i += 128)
        s_list[i] = g_edge_nodes[e * EDGE_CAP + i];
    __syncthreads();

    const float4* Xw4 = (const float4*)g_Xw;   // row stride 32
    float4 a0 = {0,0,0,0}, a1 = {0,0,0,0}, a2 = {0,0,0,0}, a3 = {0,0,0,0};
    int i = w;
    for (; i + 12 < L; i += 16) {
        int n0 = s_list[i], n1 = s_list[i + 4], n2 = s_list[i + 8], n3 = s_list[i + 12];
        a0 = f4add(a0, Xw4[n0 * 32 + l]);
        a1 = f4add(a1, Xw4[n1 * 32 + l]);
        a2 = f4add(a2, Xw4[n2 * 32 + l]);
        a3 = f4add(a3, Xw4[n3 * 32 + l]);
    }
    for (; i < L; i += 4)
        a0 = f4add(a0, Xw4[(int)s_list[i] * 32 + l]);

    s_red[w][l] = f4add(f4add(a0, a1), f4add(a2, a3));
    __syncthreads();

    if (w == 0) {
        float4 r = f4add(f4add(s_red[0][l], s_red[1][l]),
                         f4add(s_red[2][l], s_red[3][l]));
        float inv = __fdividef(1.0f, (float)cnt + 1e-12f);
        r.x *= inv; r.y *= inv; r.z *= inv; r.w *= inv;
        ((float4*)g_M)[e * 32 + l] = r;
    }
}

// ---------------- K4: block-per-node, 4 warps; also re-zeros edge_cnt ----
__global__ __launch_bounds__(128) void k_node_gather(const float* __restrict__ bias,
                                                     float* __restrict__ out) {
    __shared__ unsigned short s_list[NODE_CAP];
    __shared__ float4 s_red[4][32];
    int n = blockIdx.x;
    int tid = threadIdx.x;
    int w = tid >> 5, l = tid & 31;

    // Re-establish the "g_edge_cnt == 0" invariant for the next graph replay.
    if (tid == 0 && n < Ee) g_edge_cnt[n] = 0;

    int cnt = g_node_cnt[n];
    int L = cnt < NODE_CAP ? cnt : NODE_CAP;
    for (int i = tid; i < L; i += 128)
        s_list[i] = g_node_edges[n * NODE_CAP + i];
    __syncthreads();

    const float4* M4 = (const float4*)g_M;   // row stride 32
    float4 a0 = {0,0,0,0}, a1 = {0,0,0,0}, a2 = {0,0,0,0}, a3 = {0,0,0,0};
    int i = w;
    for (; i + 12 < L; i += 16) {
        int e0 = s_list[i], e1 = s_list[i + 4], e2 = s_list[i + 8], e3 = s_list[i + 12];
        a0 = f4add(a0, M4[e0 * 32 + l]);
        a1 = f4add(a1, M4[e1 * 32 + l]);
        a2 = f4add(a2, M4[e2 * 32 + l]);
        a3 = f4add(a3, M4[e3 * 32 + l]);
    }
    for (; i < L; i += 4)
        a0 = f4add(a0, M4[(int)s_list[i] * 32 + l]);

    s_red[w][l] = f4add(f4add(a0, a1), f4add(a2, a3));
    __syncthreads();

    if (w == 0) {
        float4 r = f4add(f4add(s_red[0][l], s_red[1][l]),
                         f4add(s_red[2][l], s_red[3][l]));
        float inv = __fdividef(1.0f, (float)cnt + 1e-12f);
        float4 b = ((const float4*)bias)[l];
        r.x = fmaxf(r.x * inv + b.x, 0.0f);
        r.y = fmaxf(r.y * inv + b.y, 0.0f);
        r.z = fmaxf(r.z * inv + b.z, 0.0f);
        r.w = fmaxf(r.w * inv + b.w, 0.0f);
        ((float4*)out)[n * 32 + l] = r;
    }
}

// ---------------- launch -------------------------------------------------
extern "C" void kernel_launch(void* const* d_in, const int* in_sizes, int n_in,
                              void* d_out, int out_size) {
    const float* X = (const float*)d_in[0];
    const float* H = (const float*)d_in[1];
    const float* W = (const float*)d_in[2];
    const float* bias = (const float*)d_in[3];
    float* out = (float*)d_out;

    dim3 xwb(32, 8);
    k_xw<<<Nn / 32, xwb>>>(X, W);
    k_nop<<<1, 1>>>();   // probes: keep k_scan_h in the ncu slot
    k_nop<<<1, 1>>>();
    k_scan_h<<<Nn / 2, 256>>>(H);
    k_edge_gather<<<Ee, 128>>>();
    k_node_gather<<<Nn, 128>>>(bias, out);
}

// round 10
// speedup vs baseline: 1.2565x; 1.2565x over previous
#include <cuda_runtime.h>
#include <stdint.h>

// Problem constants (fixed by the dataset).
#define Nn 20000
#define Ee 5000
#define Ff 128
#define NODE_CAP 256   // max edges per node (Binom(5000,.01): mean 50, max ~81)
#define EDGE_CAP 512   // max nodes per edge (Binom(20000,.01): mean 200, max ~260)

// ---------------- device scratch (no allocations allowed) ----------------
__device__ float g_Xw[Nn * Ff];                        // 10.24 MB
__device__ float g_M[Ee * Ff];                         //  2.56 MB
__device__ int   g_node_cnt[Nn];
__device__ int   g_edge_cnt[Ee];    // zero at start of every run (see k_node_gather)
__device__ unsigned short g_node_edges[Nn * NODE_CAP];
__device__ unsigned short g_edge_nodes[Ee * EDGE_CAP];

__device__ __forceinline__ float4 f4add(float4 a, float4 b) {
    a.x += b.x; a.y += b.y; a.z += b.z; a.w += b.w; return a;
}

// ---------------- nop probe (keeps the scan in the profiled slot) --------
__global__ void k_nop() {}

// ---------------- K1: Xw = X @ W, 4x4 register micro-tile ----------------
__global__ __launch_bounds__(256) void k_xw(const float* __restrict__ X,
                                            const float* __restrict__ W) {
    __shared__ float xs[32][Ff];   // 16 KB X tile
    int tx = threadIdx.x;          // 0..31 (col group)
    int ty = threadIdx.y;          // 0..7  (row group)
    int tid = ty * 32 + tx;
    int row0 = blockIdx.x * 32;

    const float4* X4 = (const float4*)(X + (size_t)row0 * Ff);
#pragma unroll
    for (int k = 0; k < 4; k++) {
        int v = tid + k * 256;
        int r = v >> 5, c4 = v & 31;
        ((float4*)&xs[r][0])[c4] = X4[r * 32 + c4];
    }
    __syncthreads();

    const float4* W4 = (const float4*)W;
    float4 acc0 = {0,0,0,0}, acc1 = {0,0,0,0}, acc2 = {0,0,0,0}, acc3 = {0,0,0,0};
    int r0 = 4 * ty;

#pragma unroll 4
    for (int k = 0; k < Ff; k++) {
        float4 w = W4[k * 32 + tx];
        float x0 = xs[r0 + 0][k];
        float x1 = xs[r0 + 1][k];
        float x2 = xs[r0 + 2][k];
        float x3 = xs[r0 + 3][k];
        acc0.x += x0 * w.x; acc0.y += x0 * w.y; acc0.z += x0 * w.z; acc0.w += x0 * w.w;
        acc1.x += x1 * w.x; acc1.y += x1 * w.y; acc1.z += x1 * w.z; acc1.w += x1 * w.w;
        acc2.x += x2 * w.x; acc2.y += x2 * w.y; acc2.z += x2 * w.z; acc2.w += x2 * w.w;
        acc3.x += x3 * w.x; acc3.y += x3 * w.y; acc3.z += x3 * w.z; acc3.w += x3 * w.w;
    }

    float4* O4 = (float4*)g_Xw;
    int orow = row0 + r0;
    O4[(orow + 0) * 32 + tx] = acc0;
    O4[(orow + 1) * 32 + tx] = acc1;
    O4[(orow + 2) * 32 + tx] = acc2;
    O4[(orow + 3) * 32 + tx] = acc3;
}

// ---------------- K2: scan H, register preload + prefix-scan slots -------
// One block per node row (R7 shape: grid 20000, occ ~94%). Each thread
// preloads its 5 uint4 (MLP=5), counts its nonzeros from registers, a
// shfl/block prefix-scan assigns deterministic node-list slots (NO smem
// atomics), then pass 2 emits entries. H entries are exactly 0.0f/1.0f.
__global__ __launch_bounds__(256) void k_scan_h(const float* __restrict__ H) {
    __shared__ int s_warp_base[8];
    int n = blockIdx.x;
    int tid = threadIdx.x;
    int lane = tid & 31, wid = tid >> 5;

    const uint4* row = (const uint4*)(H + (size_t)n * Ee);
    const int nvec = Ee / 4;  // 1250

    uint4 v[5];
#pragma unroll
    for (int k = 0; k < 5; k++) {
        int i = tid + k * 256;
        v[k] = (i < nvec) ? row[i] : make_uint4(0u, 0u, 0u, 0u);
    }

    // per-thread nonzero count (pure ALU)
    int cnt = 0;
#pragma unroll
    for (int k = 0; k < 5; k++)
        cnt += (v[k].x != 0u) + (v[k].y != 0u) + (v[k].z != 0u) + (v[k].w != 0u);

    // warp inclusive scan
    int incl = cnt;
#pragma unroll
    for (int d = 1; d < 32; d <<= 1) {
        int t = __shfl_up_sync(0xffffffffu, incl, d);
        if (lane >= d) incl += t;
    }
    if (lane == 31) s_warp_base[wid] = incl;
    __syncthreads();
    if (tid == 0) {
        int acc = 0;
#pragma unroll
        for (int w = 0; w < 8; w++) { int t = s_warp_base[w]; s_warp_base[w] = acc; acc += t; }
        g_node_cnt[n] = acc;
    }
    __syncthreads();
    int j = s_warp_base[wid] + incl - cnt;   // exclusive slot base for this thread

    // pass 2: emit from registers; OR-skip all-zero 16B chunks (~96%)
#pragma unroll
    for (int k = 0; k < 5; k++) {
        if ((v[k].x | v[k].y | v[k].z | v[k].w) != 0u) {
            unsigned vals[4] = {v[k].x, v[k].y, v[k].z, v[k].w};
#pragma unroll
            for (int c = 0; c < 4; c++) {
                if (vals[c] != 0u) {
                    int e = (tid + k * 256) * 4 + c;
                    if (j < NODE_CAP) g_node_edges[n * NODE_CAP + j] = (unsigned short)e;
                    j++;
                    int kk = atomicAdd(&g_edge_cnt[e], 1);
                    if (kk < EDGE_CAP) g_edge_nodes[e * EDGE_CAP + kk] = (unsigned short)n;
                }
            }
        }
    }
}

// ---------------- K3: block-per-edge, 4 warps (proven shape) -------------
__global__ __launch_bounds__(128) void k_edge_gather() {
    __shared__ unsigned short s_list[EDGE_CAP];
    __shared__ float4 s_red[4][32];
    int e = blockIdx.x;
    int tid = threadIdx.x;
    int w = tid >> 5, l = tid & 31;
    int cnt = g_edge_cnt[e];
    int L = cnt < EDGE_CAP ? cnt : EDGE_CAP;
    for (int i = tid; i < L; i += 128)
        s_list[i] = g_edge_nodes[e * EDGE_CAP + i];
    __syncthreads();

    const float4* Xw4 = (const float4*)g_Xw;   // row stride 32
    float4 a0 = {0,0,0,0}, a1 = {0,0,0,0}, a2 = {0,0,0,0}, a3 = {0,0,0,0};
    int i = w;
    for (; i + 12 < L; i += 16) {
        int n0 = s_list[i], n1 = s_list[i + 4], n2 = s_list[i + 8], n3 = s_list[i + 12];
        a0 = f4add(a0, Xw4[n0 * 32 + l]);
        a1 = f4add(a1, Xw4[n1 * 32 + l]);
        a2 = f4add(a2, Xw4[n2 * 32 + l]);
        a3 = f4add(a3, Xw4[n3 * 32 + l]);
    }
    for (; i < L; i += 4)
        a0 = f4add(a0, Xw4[(int)s_list[i] * 32 + l]);

    s_red[w][l] = f4add(f4add(a0, a1), f4add(a2, a3));
    __syncthreads();

    if (w == 0) {
        float4 r = f4add(f4add(s_red[0][l], s_red[1][l]),
                         f4add(s_red[2][l], s_red[3][l]));
        float inv = __fdividef(1.0f, (float)cnt + 1e-12f);
        r.x *= inv; r.y *= inv; r.z *= inv; r.w *= inv;
        ((float4*)g_M)[e * 32 + l] = r;
    }
}

// ---------------- K4: block-per-node, 4 warps; also re-zeros edge_cnt ----
__global__ __launch_bounds__(128) void k_node_gather(const float* __restrict__ bias,
                                                     float* __restrict__ out) {
    __shared__ unsigned short s_list[NODE_CAP];
    __shared__ float4 s_red[4][32];
    int n = blockIdx.x;
    int tid = threadIdx.x;
    int w = tid >> 5, l = tid & 31;

    // Re-establish the "g_edge_cnt == 0" invariant for the next graph replay.
    if (tid == 0 && n < Ee) g_edge_cnt[n] = 0;

    int cnt = g_node_cnt[n];
    int L = cnt < NODE_CAP ? cnt : NODE_CAP;
    for (int i = tid; i < L; i += 128)
        s_list[i] = g_node_edges[n * NODE_CAP + i];
    __syncthreads();

    const float4* M4 = (const float4*)g_M;   // row stride 32
    float4 a0 = {0,0,0,0}, a1 = {0,0,0,0}, a2 = {0,0,0,0}, a3 = {0,0,0,0};
    int i = w;
    for (; i + 12 < L; i += 16) {
        int e0 = s_list[i], e1 = s_list[i + 4], e2 = s_list[i + 8], e3 = s_list[i + 12];
        a0 = f4add(a0, M4[e0 * 32 + l]);
        a1 = f4add(a1, M4[e1 * 32 + l]);
        a2 = f4add(a2, M4[e2 * 32 + l]);
        a3 = f4add(a3, M4[e3 * 32 + l]);
    }
    for (; i < L; i += 4)
        a0 = f4add(a0, M4[(int)s_list[i] * 32 + l]);

    s_red[w][l] = f4add(f4add(a0, a1), f4add(a2, a3));
    __syncthreads();

    if (w == 0) {
        float4 r = f4add(f4add(s_red[0][l], s_red[1][l]),
                         f4add(s_red[2][l], s_red[3][l]));
        float inv = __fdividef(1.0f, (float)cnt + 1e-12f);
        float4 b = ((const float4*)bias)[l];
        r.x = fmaxf(r.x * inv + b.x, 0.0f);
        r.y = fmaxf(r.y * inv + b.y, 0.0f);
        r.z = fmaxf(r.z * inv + b.z, 0.0f);
        r.w = fmaxf(r.w * inv + b.w, 0.0f);
        ((float4*)out)[n * 32 + l] = r;
    }
}

// ---------------- launch -------------------------------------------------
extern "C" void kernel_launch(void* const* d_in, const int* in_sizes, int n_in,
                              void* d_out, int out_size) {
    const float* X = (const float*)d_in[0];
    const float* H = (const float*)d_in[1];
    const float* W = (const float*)d_in[2];
    const float* bias = (const float*)d_in[3];
    float* out = (float*)d_out;

    dim3 xwb(32, 8);
    k_xw<<<Nn / 32, xwb>>>(X, W);
    k_nop<<<1, 1>>>();   // probes: keep k_scan_h in the ncu slot
    k_nop<<<1, 1>>>();
    k_scan_h<<<Nn, 256>>>(H);
    k_edge_gather<<<Ee, 128>>>();
    k_node_gather<<<Nn, 128>>>(bias, out);
}

// round 11
// speedup vs baseline: 1.4874x; 1.1838x over previous
#include <cuda_runtime.h>
#include <cuda_bf16.h>
#include <stdint.h>

// Problem constants (fixed by the dataset).
#define Nn 20000
#define Ee 5000
#define Ff 128
#define NODE_CAP 256   // max edges per node (Binom(5000,.01): mean 50, max ~81)
#define EDGE_CAP 512   // max nodes per edge (Binom(20000,.01): mean 200, max ~260)

// ---------------- device scratch (no allocations allowed) ----------------
// Xw and M stored as bf16: one uint2 = 4 features; 32 uint2 per 128-f row.
__device__ uint2 g_Xw2[Nn * 32];                       // 5.12 MB
__device__ uint2 g_M2[Ee * 32];                        // 1.28 MB
__device__ int   g_node_cnt[Nn];
__device__ int   g_edge_cnt[Ee];    // zero at start of every run (see k_node_gather)
__device__ unsigned short g_node_edges[Nn * NODE_CAP];
__device__ unsigned short g_edge_nodes[Ee * EDGE_CAP];

// bf16x4 accumulate: acc += v, two HADD2 ops, no conversions.
__device__ __forceinline__ void hacc(uint2& acc, uint2 v) {
    __nv_bfloat162& alo = reinterpret_cast<__nv_bfloat162&>(acc.x);
    __nv_bfloat162& ahi = reinterpret_cast<__nv_bfloat162&>(acc.y);
    alo = __hadd2(alo, reinterpret_cast<const __nv_bfloat162&>(v.x));
    ahi = __hadd2(ahi, reinterpret_cast<const __nv_bfloat162&>(v.y));
}

// bf16x4 (uint2) -> float4
__device__ __forceinline__ float4 h2f4(uint2 a) {
    float2 lo = __bfloat1622float2(reinterpret_cast<const __nv_bfloat162&>(a.x));
    float2 hi = __bfloat1622float2(reinterpret_cast<const __nv_bfloat162&>(a.y));
    return make_float4(lo.x, lo.y, hi.x, hi.y);
}

// float4 -> bf16x4 (uint2)
__device__ __forceinline__ uint2 f42h(float4 a) {
    __nv_bfloat162 lo = __floats2bfloat162_rn(a.x, a.y);
    __nv_bfloat162 hi = __floats2bfloat162_rn(a.z, a.w);
    uint2 r;
    r.x = reinterpret_cast<const unsigned&>(lo);
    r.y = reinterpret_cast<const unsigned&>(hi);
    return r;
}

__device__ __forceinline__ float4 f4add(float4 a, float4 b) {
    a.x += b.x; a.y += b.y; a.z += b.z; a.w += b.w; return a;
}

// ---------------- K1: Xw = X @ W, 4x4 micro-tile, bf16 store -------------
__global__ __launch_bounds__(256) void k_xw(const float* __restrict__ X,
                                            const float* __restrict__ W) {
    __shared__ float xs[32][Ff];   // 16 KB X tile
    int tx = threadIdx.x;          // 0..31 (col group)
    int ty = threadIdx.y;          // 0..7  (row group)
    int tid = ty * 32 + tx;
    int row0 = blockIdx.x * 32;

    const float4* X4 = (const float4*)(X + (size_t)row0 * Ff);
#pragma unroll
    for (int k = 0; k < 4; k++) {
        int v = tid + k * 256;
        int r = v >> 5, c4 = v & 31;
        ((float4*)&xs[r][0])[c4] = X4[r * 32 + c4];
    }
    __syncthreads();

    const float4* W4 = (const float4*)W;
    float4 acc0 = {0,0,0,0}, acc1 = {0,0,0,0}, acc2 = {0,0,0,0}, acc3 = {0,0,0,0};
    int r0 = 4 * ty;

#pragma unroll 4
    for (int k = 0; k < Ff; k++) {
        float4 w = W4[k * 32 + tx];
        float x0 = xs[r0 + 0][k];
        float x1 = xs[r0 + 1][k];
        float x2 = xs[r0 + 2][k];
        float x3 = xs[r0 + 3][k];
        acc0.x += x0 * w.x; acc0.y += x0 * w.y; acc0.z += x0 * w.z; acc0.w += x0 * w.w;
        acc1.x += x1 * w.x; acc1.y += x1 * w.y; acc1.z += x1 * w.z; acc1.w += x1 * w.w;
        acc2.x += x2 * w.x; acc2.y += x2 * w.y; acc2.z += x2 * w.z; acc2.w += x2 * w.w;
        acc3.x += x3 * w.x; acc3.y += x3 * w.y; acc3.z += x3 * w.z; acc3.w += x3 * w.w;
    }

    int orow = row0 + r0;
    g_Xw2[(orow + 0) * 32 + tx] = f42h(acc0);
    g_Xw2[(orow + 1) * 32 + tx] = f42h(acc1);
    g_Xw2[(orow + 2) * 32 + tx] = f42h(acc2);
    g_Xw2[(orow + 3) * 32 + tx] = f42h(acc3);
}

// ---------------- K2: scan H, register preload + prefix-scan slots -------
// (R10-proven: 84.6us) One block per node row; MLP=5 preload; shfl prefix
// scan assigns node-list slots with no smem atomics. H entries exactly 0/1.
__global__ __launch_bounds__(256) void k_scan_h(const float* __restrict__ H) {
    __shared__ int s_warp_base[8];
    int n = blockIdx.x;
    int tid = threadIdx.x;
    int lane = tid & 31, wid = tid >> 5;

    const uint4* row = (const uint4*)(H + (size_t)n * Ee);
    const int nvec = Ee / 4;  // 1250

    uint4 v[5];
#pragma unroll
    for (int k = 0; k < 5; k++) {
        int i = tid + k * 256;
        v[k] = (i < nvec) ? row[i] : make_uint4(0u, 0u, 0u, 0u);
    }

    int cnt = 0;
#pragma unroll
    for (int k = 0; k < 5; k++)
        cnt += (v[k].x != 0u) + (v[k].y != 0u) + (v[k].z != 0u) + (v[k].w != 0u);

    int incl = cnt;
#pragma unroll
    for (int d = 1; d < 32; d <<= 1) {
        int t = __shfl_up_sync(0xffffffffu, incl, d);
        if (lane >= d) incl += t;
    }
    if (lane == 31) s_warp_base[wid] = incl;
    __syncthreads();
    if (tid == 0) {
        int acc = 0;
#pragma unroll
        for (int w = 0; w < 8; w++) { int t = s_warp_base[w]; s_warp_base[w] = acc; acc += t; }
        g_node_cnt[n] = acc;
    }
    __syncthreads();
    int j = s_warp_base[wid] + incl - cnt;

#pragma unroll
    for (int k = 0; k < 5; k++) {
        if ((v[k].x | v[k].y | v[k].z | v[k].w) != 0u) {
            unsigned vals[4] = {v[k].x, v[k].y, v[k].z, v[k].w};
#pragma unroll
            for (int c = 0; c < 4; c++) {
                if (vals[c] != 0u) {
                    int e = (tid + k * 256) * 4 + c;
                    if (j < NODE_CAP) g_node_edges[n * NODE_CAP + j] = (unsigned short)e;
                    j++;
                    int kk = atomicAdd(&g_edge_cnt[e], 1);
                    if (kk < EDGE_CAP) g_edge_nodes[e * EDGE_CAP + kk] = (unsigned short)n;
                }
            }
        }
    }
}

// ---------------- K3: block-per-edge, bf16 HADD2 gather ------------------
// 4 warps split the list 4-deep -> 16 short bf16 accumulation chains per
// lane-feature; chains combine in fp32. 1 LDG.64 + 2 HADD2 per entry.
__global__ __launch_bounds__(128) void k_edge_gather() {
    __shared__ unsigned short s_list[EDGE_CAP];
    __shared__ float4 s_red[4][32];
    int e = blockIdx.x;
    int tid = threadIdx.x;
    int w = tid >> 5, l = tid & 31;
    int cnt = g_edge_cnt[e];
    int L = cnt < EDGE_CAP ? cnt : EDGE_CAP;
    for (int i = tid; i < L; i += 128)
        s_list[i] = g_edge_nodes[e * EDGE_CAP + i];
    __syncthreads();

    uint2 a0 = {0,0}, a1 = {0,0}, a2 = {0,0}, a3 = {0,0};
    int i = w;
    for (; i + 12 < L; i += 16) {
        int n0 = s_list[i], n1 = s_list[i + 4], n2 = s_list[i + 8], n3 = s_list[i + 12];
        hacc(a0, __ldg(&g_Xw2[n0 * 32 + l]));
        hacc(a1, __ldg(&g_Xw2[n1 * 32 + l]));
        hacc(a2, __ldg(&g_Xw2[n2 * 32 + l]));
        hacc(a3, __ldg(&g_Xw2[n3 * 32 + l]));
    }
    for (; i < L; i += 4)
        hacc(a0, __ldg(&g_Xw2[(int)s_list[i] * 32 + l]));

    // combine the 4 chains in fp32
    float4 r = f4add(f4add(h2f4(a0), h2f4(a1)), f4add(h2f4(a2), h2f4(a3)));
    s_red[w][l] = r;
    __syncthreads();

    if (w == 0) {
        float4 s = f4add(f4add(s_red[0][l], s_red[1][l]),
                         f4add(s_red[2][l], s_red[3][l]));
        float inv = __fdividef(1.0f, (float)cnt + 1e-12f);
        s.x *= inv; s.y *= inv; s.z *= inv; s.w *= inv;
        g_M2[e * 32 + l] = f42h(s);
    }
}

// ---------------- K4: block-per-node, bf16 HADD2 gather, fp32 out --------
__global__ __launch_bounds__(128) void k_node_gather(const float* __restrict__ bias,
                                                     float* __restrict__ out) {
    __shared__ unsigned short s_list[NODE_CAP];
    __shared__ float4 s_red[4][32];
    int n = blockIdx.x;
    int tid = threadIdx.x;
    int w = tid >> 5, l = tid & 31;

    // Re-establish the "g_edge_cnt == 0" invariant for the next graph replay.
    if (tid == 0 && n < Ee) g_edge_cnt[n] = 0;

    int cnt = g_node_cnt[n];
    int L = cnt < NODE_CAP ? cnt : NODE_CAP;
    for (int i = tid; i < L; i += 128)
        s_list[i] = g_node_edges[n * NODE_CAP + i];
    __syncthreads();

    uint2 a0 = {0,0}, a1 = {0,0}, a2 = {0,0}, a3 = {0,0};
    int i = w;
    for (; i + 12 < L; i += 16) {
        int e0 = s_list[i], e1 = s_list[i + 4], e2 = s_list[i + 8], e3 = s_list[i + 12];
        hacc(a0, __ldg(&g_M2[e0 * 32 + l]));
        hacc(a1, __ldg(&g_M2[e1 * 32 + l]));
        hacc(a2, __ldg(&g_M2[e2 * 32 + l]));
        hacc(a3, __ldg(&g_M2[e3 * 32 + l]));
    }
    for (; i < L; i += 4)
        hacc(a0, __ldg(&g_M2[(int)s_list[i] * 32 + l]));

    float4 r = f4add(f4add(h2f4(a0), h2f4(a1)), f4add(h2f4(a2), h2f4(a3)));
    s_red[w][l] = r;
    __syncthreads();

    if (w == 0) {
        float4 r2 = f4add(f4add(s_red[0][l], s_red[1][l]),
                          f4add(s_red[2][l], s_red[3][l]));
        float inv = __fdividef(1.0f, (float)cnt + 1e-12f);
        float4 b = ((const float4*)bias)[l];
        r2.x = fmaxf(r2.x * inv + b.x, 0.0f);
        r2.y = fmaxf(r2.y * inv + b.y, 0.0f);
        r2.z = fmaxf(r2.z * inv + b.z, 0.0f);
        r2.w = fmaxf(r2.w * inv + b.w, 0.0f);
        ((float4*)out)[n * 32 + l] = r2;
    }
}

// ---------------- launch -------------------------------------------------
extern "C" void kernel_launch(void* const* d_in, const int* in_sizes, int n_in,
                              void* d_out, int out_size) {
    const float* X = (const float*)d_in[0];
    const float* H = (const float*)d_in[1];
    const float* W = (const float*)d_in[2];
    const float* bias = (const float*)d_in[3];
    float* out = (float*)d_out;

    dim3 xwb(32, 8);
    k_xw<<<Nn / 32, xwb>>>(X, W);
    k_scan_h<<<Nn, 256>>>(H);
    k_edge_gather<<<Ee, 128>>>();
    k_node_gather<<<Nn, 128>>>(bias, out);   // profiled (4th) slot this round
}